// round 1
// baseline (speedup 1.0000x reference)
#include <cuda_runtime.h>
#include <math.h>

#define BB 2
#define LL 128
#define DD 256
#define HH 256

// Output offsets (floats) in the packed d_out, reference tuple order.
#define OFF_ZQ2   0
#define OFF_W1P   65536
#define OFF_B1P   196608
#define OFF_W2P   197120
#define OFF_B2P   328192
#define OFF_MGW1  328704
#define OFF_MGB1  459776
#define OFF_MGW2  460288
#define OFF_MGB2  591360

// Scratch (device globals: allocation-free)
__device__ float g_q[BB*LL*DD];
__device__ float g_k[BB*LL*DD];
__device__ float g_v[BB*LL*DD];
__device__ float g_lr[BB*LL];
__device__ float g_logmom[BB*LL];
__device__ float g_logwd[BB*LL];
__device__ float g_cm[BB*LL];
__device__ float g_cd[BB*LL];
__device__ float g_momcum[BB*LL];
__device__ float g_wdcum[BB*LL];
__device__ float g_c[BB*LL];
__device__ float g_A[BB*LL*LL];
__device__ float g_X2[BB*LL*HH];
__device__ float g_gz1[BB*LL*HH];
__device__ float g_gz2[BB*LL*DD];
__device__ float g_sq[BB*LL*HH];

__device__ __forceinline__ float softplusf(float x){
    return fmaxf(x, 0.f) + log1pf(expf(-fabsf(x)));
}

// K1: q,k,v projections + scalar gates (lr, log_mom, log_wd). One block per (b,l).
__global__ void k_proj(const float* __restrict__ x,
    const float* __restrict__ Wq, const float* __restrict__ bq,
    const float* __restrict__ Wk, const float* __restrict__ bk,
    const float* __restrict__ Wv, const float* __restrict__ bv,
    const float* __restrict__ Wlr, const float* __restrict__ blr,
    const float* __restrict__ Wm, const float* __restrict__ bm,
    const float* __restrict__ Wd, const float* __restrict__ bd,
    float lrshift)
{
    int bl = blockIdx.x;
    int t = threadIdx.x;
    __shared__ float xs[DD];
    __shared__ float r0[256], r1[256], r2[256];
    xs[t] = x[bl*DD + t];
    __syncthreads();
    float aq = 0.f, ak = 0.f, av = 0.f;
    #pragma unroll 4
    for (int i = 0; i < DD; i++){
        float xv = xs[i];
        aq = fmaf(xv, Wq[i*DD + t], aq);
        ak = fmaf(xv, Wk[i*DD + t], ak);
        av = fmaf(xv, Wv[i*DD + t], av);
    }
    g_q[bl*DD + t] = aq + bq[t];
    g_k[bl*DD + t] = ak + bk[t];
    g_v[bl*DD + t] = av + bv[t];
    r0[t] = xs[t] * Wlr[t];
    r1[t] = xs[t] * Wm[t];
    r2[t] = xs[t] * Wd[t];
    __syncthreads();
    for (int s = 128; s > 0; s >>= 1){
        if (t < s){ r0[t] += r0[t+s]; r1[t] += r1[t+s]; r2[t] += r2[t+s]; }
        __syncthreads();
    }
    if (t == 0){
        g_lr[bl]     = softplusf(r0[0] + blr[0] + lrshift);
        g_logmom[bl] = -softplusf(-(r1[0] + bm[0]));
        g_logwd[bl]  = -softplusf(r2[0] + bd[0]);
    }
}

// K2: fast-weight forward + per-token gradients. One block per (b,l).
__global__ void k_fwd(const float* __restrict__ W1, const float* __restrict__ b1,
                      const float* __restrict__ W2, const float* __restrict__ b2)
{
    int bl = blockIdx.x;
    int b = bl / LL;
    int t = threadIdx.x;
    __shared__ float krow[DD];
    __shared__ float x2s[HH];
    __shared__ float gz2s[DD];
    krow[t] = g_k[bl*DD + t];
    __syncthreads();
    // Z1[h=t] = W1[b,h,:] . krow + b1
    const float* w1r = W1 + (b*HH + t)*DD;
    float z1 = b1[b*HH + t];
    #pragma unroll 4
    for (int i = 0; i < DD; i++) z1 = fmaf(w1r[i], krow[i], z1);
    float sig = 1.f / (1.f + expf(-z1));
    float x2 = z1 * sig;
    x2s[t] = x2;
    __syncthreads();
    // Z2[d=t], gz2
    const float* w2r = W2 + (b*DD + t)*HH;
    float z2 = b2[b*DD + t];
    #pragma unroll 4
    for (int h = 0; h < HH; h++) z2 = fmaf(w2r[h], x2s[h], z2);
    float gz2 = z2 - g_v[bl*DD + t];
    gz2s[t] = gz2;
    g_gz2[bl*DD + t] = gz2;
    __syncthreads();
    // gx2[h=t] = sum_d gz2[d] * W2[b,d,t]  (coalesced over t)
    float gx2 = 0.f;
    const float* w2c = W2 + b*DD*HH + t;
    #pragma unroll 4
    for (int d = 0; d < DD; d++) gx2 = fmaf(gz2s[d], w2c[d*HH], gx2);
    float sb = x2 + sig * (1.f - x2);   // silu_backward with s=silu(z1)
    g_gz1[bl*HH + t] = gx2 * sb;
    g_X2[bl*HH + t] = x2;
}

// K3: inclusive cumsums of gates. One block per batch, L threads.
__global__ void k_scan()
{
    int b = blockIdx.x;
    int l = threadIdx.x;
    __shared__ float sm[LL], sd[LL];
    sm[l] = g_logmom[b*LL + l];
    sd[l] = g_logwd[b*LL + l];
    __syncthreads();
    float cm = 0.f, cd = 0.f;
    for (int i = 0; i <= l; i++){ cm += sm[i]; cd += sd[i]; }
    g_cm[b*LL + l] = cm;
    g_cd[b*LL + l] = cd;
    g_momcum[b*LL + l] = expf(cm);
    g_wdcum[b*LL + l]  = expf(cd);
}

// K4: A = Dm@M (lower-tri LxL), c = Dm@mom_cum. One block per (l,b), L threads.
__global__ void k_A()
{
    int l = blockIdx.x, b = blockIdx.y;
    int m = threadIdx.x;
    __shared__ float cm[LL], cd[LL], red[LL];
    cm[m] = g_cm[b*LL + m];
    cd[m] = g_cd[b*LL + m];
    __syncthreads();
    float a = 0.f;
    if (m <= l){
        float base = cd[l] - cm[m];
        float s = 0.f;
        for (int j = m; j <= l; j++) s += expf(base - cd[j] + cm[j]);
        a = s;
    }
    g_A[(b*LL + l)*LL + m] = a;
    red[m] = (m <= l) ? expf(cd[l] - cd[m] + cm[m]) : 0.f;
    __syncthreads();
    for (int s = 64; s > 0; s >>= 1){
        if (m < s) red[m] += red[m + s];
        __syncthreads();
    }
    if (m == 0) g_c[b*LL + l] = red[0];
}

// K5: Zq1 & sq via decomposed per-token-weight query pass. One block per (b,l).
__global__ void k_zq1(const float* __restrict__ W1, const float* __restrict__ b1,
                      const float* __restrict__ mW1, const float* __restrict__ mb1)
{
    int bl = blockIdx.x;
    int b = bl / LL, l = bl % LL;
    int t = threadIdx.x;
    __shared__ float qrow[DD];
    __shared__ float p1[LL];
    qrow[t] = g_q[bl*DD + t];
    __syncthreads();
    if (t < LL){
        float val = 0.f;
        if (t <= l){
            const float* kr = g_k + (b*LL + t)*DD;
            float kq = 0.f;
            #pragma unroll 4
            for (int i = 0; i < DD; i++) kq = fmaf(kr[i], qrow[i], kq);
            val = g_A[(b*LL + l)*LL + t] * g_lr[b*LL + t] * (1.f + kq);
        }
        p1[t] = val;
    }
    __syncthreads();
    float acc = 0.f;
    const float* gz = g_gz1 + b*LL*HH + t;
    for (int m = 0; m <= l; m++) acc = fmaf(p1[m], gz[m*HH], acc);
    const float* w1r  = W1  + (b*HH + t)*DD;
    const float* mw1r = mW1 + (b*HH + t)*DD;
    float w1q = 0.f, mw1q = 0.f;
    #pragma unroll 4
    for (int i = 0; i < DD; i++){
        w1q  = fmaf(w1r[i],  qrow[i], w1q);
        mw1q = fmaf(mw1r[i], qrow[i], mw1q);
    }
    float cl = g_c[bl], wdl = g_wdcum[bl];
    float zq1 = acc - cl * (mw1q + mb1[b*HH + t]) + wdl * (w1q + b1[b*HH + t]);
    float sig = 1.f / (1.f + expf(-zq1));
    g_sq[bl*HH + t] = zq1 * sig;
}

// K6: Zq2 (first output block). One block per (b,l).
__global__ void k_zq2(const float* __restrict__ W2, const float* __restrict__ b2,
                      const float* __restrict__ mW2, const float* __restrict__ mb2,
                      float* __restrict__ out)
{
    int bl = blockIdx.x;
    int b = bl / LL, l = bl % LL;
    int t = threadIdx.x;
    __shared__ float sqrow[HH];
    __shared__ float p2[LL];
    sqrow[t] = g_sq[bl*HH + t];
    __syncthreads();
    if (t < LL){
        float val = 0.f;
        if (t <= l){
            const float* xr = g_X2 + (b*LL + t)*HH;
            float xsum = 0.f;
            #pragma unroll 4
            for (int i = 0; i < HH; i++) xsum = fmaf(xr[i], sqrow[i], xsum);
            val = g_A[(b*LL + l)*LL + t] * g_lr[b*LL + t] * (1.f + xsum);
        }
        p2[t] = val;
    }
    __syncthreads();
    float acc = 0.f;
    const float* gz = g_gz2 + b*LL*DD + t;
    for (int m = 0; m <= l; m++) acc = fmaf(p2[m], gz[m*DD], acc);
    const float* w2r  = W2  + (b*DD + t)*HH;
    const float* mw2r = mW2 + (b*DD + t)*HH;
    float w2s = 0.f, mw2s = 0.f;
    #pragma unroll 4
    for (int h = 0; h < HH; h++){
        w2s  = fmaf(w2r[h],  sqrow[h], w2s);
        mw2s = fmaf(mw2r[h], sqrow[h], mw2s);
    }
    float cl = g_c[bl], wdl = g_wdcum[bl];
    out[OFF_ZQ2 + bl*DD + t] =
        acc - cl * (mw2s + mb2[b*DD + t]) + wdl * (w2s + b2[b*DD + t]);
}

// K7: last-token W1p / mgW1. One block per (b,h), D threads.
__global__ void k_w1out(const float* __restrict__ W1, const float* __restrict__ mW1,
                        float* __restrict__ out)
{
    int h = blockIdx.x, b = blockIdx.y;
    int t = threadIdx.x;
    __shared__ float ga[LL], gm[LL];
    const int rl = LL - 1;
    float cmL = g_cm[b*LL + rl];
    if (t < LL){
        float lr = g_lr[b*LL + t];
        float gz = g_gz1[(b*LL + t)*HH + h];
        ga[t] = g_A[(b*LL + rl)*LL + t] * lr * gz;
        gm[t] = expf(cmL - g_cm[b*LL + t]) * lr * gz;
    }
    __syncthreads();
    float s1 = 0.f, s2 = 0.f;
    const float* kp = g_k + b*LL*DD + t;
    #pragma unroll 4
    for (int m = 0; m < LL; m++){
        float kv = kp[m*DD];
        s1 = fmaf(ga[m], kv, s1);
        s2 = fmaf(gm[m], kv, s2);
    }
    float cL = g_c[b*LL + rl], wdL = g_wdcum[b*LL + rl], momL = g_momcum[b*LL + rl];
    float w1v  = W1[(b*HH + h)*DD + t];
    float mw1v = mW1[(b*HH + h)*DD + t];
    out[OFF_W1P  + (b*HH + h)*DD + t] = s1 - cL * mw1v + wdL * w1v;
    out[OFF_MGW1 + (b*HH + h)*DD + t] = s2 - momL * mw1v;
}

// K8: last-token W2p / mgW2. One block per (b,d), H threads.
__global__ void k_w2out(const float* __restrict__ W2, const float* __restrict__ mW2,
                        float* __restrict__ out)
{
    int d = blockIdx.x, b = blockIdx.y;
    int t = threadIdx.x;
    __shared__ float ga[LL], gm[LL];
    const int rl = LL - 1;
    float cmL = g_cm[b*LL + rl];
    if (t < LL){
        float lr = g_lr[b*LL + t];
        float gz = g_gz2[(b*LL + t)*DD + d];
        ga[t] = g_A[(b*LL + rl)*LL + t] * lr * gz;
        gm[t] = expf(cmL - g_cm[b*LL + t]) * lr * gz;
    }
    __syncthreads();
    float s1 = 0.f, s2 = 0.f;
    const float* xp = g_X2 + b*LL*HH + t;
    #pragma unroll 4
    for (int m = 0; m < LL; m++){
        float xv = xp[m*HH];
        s1 = fmaf(ga[m], xv, s1);
        s2 = fmaf(gm[m], xv, s2);
    }
    float cL = g_c[b*LL + rl], wdL = g_wdcum[b*LL + rl], momL = g_momcum[b*LL + rl];
    float w2v  = W2[(b*DD + d)*HH + t];
    float mw2v = mW2[(b*DD + d)*HH + t];
    out[OFF_W2P  + (b*DD + d)*HH + t] = s1 - cL * mw2v + wdL * w2v;
    out[OFF_MGW2 + (b*DD + d)*HH + t] = s2 - momL * mw2v;
}

// K9: last-token biases. One block per batch, 256 threads.
__global__ void k_bout(const float* __restrict__ b1, const float* __restrict__ mb1,
                       const float* __restrict__ b2, const float* __restrict__ mb2,
                       float* __restrict__ out)
{
    int b = blockIdx.x;
    int t = threadIdx.x;
    __shared__ float aw[LL], mw[LL];
    const int rl = LL - 1;
    if (t < LL){
        float lr = g_lr[b*LL + t];
        aw[t] = g_A[(b*LL + rl)*LL + t] * lr;
        mw[t] = expf(g_cm[b*LL + rl] - g_cm[b*LL + t]) * lr;
    }
    __syncthreads();
    float cL = g_c[b*LL + rl], wdL = g_wdcum[b*LL + rl], momL = g_momcum[b*LL + rl];
    // layer-1 biases (index h = t)
    float s1 = 0.f, s2 = 0.f;
    const float* gz1p = g_gz1 + b*LL*HH + t;
    #pragma unroll 4
    for (int m = 0; m < LL; m++){
        float g = gz1p[m*HH];
        s1 = fmaf(aw[m], g, s1);
        s2 = fmaf(mw[m], g, s2);
    }
    out[OFF_B1P  + b*HH + t] = s1 - cL * mb1[b*HH + t] + wdL * b1[b*HH + t];
    out[OFF_MGB1 + b*HH + t] = s2 - momL * mb1[b*HH + t];
    // layer-2 biases (index d = t)
    float s3 = 0.f, s4 = 0.f;
    const float* gz2p = g_gz2 + b*LL*DD + t;
    #pragma unroll 4
    for (int m = 0; m < LL; m++){
        float g = gz2p[m*DD];
        s3 = fmaf(aw[m], g, s3);
        s4 = fmaf(mw[m], g, s4);
    }
    out[OFF_B2P  + b*DD + t] = s3 - cL * mb2[b*DD + t] + wdL * b2[b*DD + t];
    out[OFF_MGB2 + b*DD + t] = s4 - momL * mb2[b*DD + t];
}

extern "C" void kernel_launch(void* const* d_in, const int* in_sizes, int n_in,
                              void* d_out, int out_size)
{
    const float* x   = (const float*)d_in[0];
    const float* Wq  = (const float*)d_in[1];
    const float* bq  = (const float*)d_in[2];
    const float* Wk  = (const float*)d_in[3];
    const float* bk  = (const float*)d_in[4];
    const float* Wv  = (const float*)d_in[5];
    const float* bv  = (const float*)d_in[6];
    const float* Wlr = (const float*)d_in[7];
    const float* blr = (const float*)d_in[8];
    const float* Wm  = (const float*)d_in[9];
    const float* bm  = (const float*)d_in[10];
    const float* Wd  = (const float*)d_in[11];
    const float* bd  = (const float*)d_in[12];
    const float* W1  = (const float*)d_in[13];
    const float* b1  = (const float*)d_in[14];
    const float* W2  = (const float*)d_in[15];
    const float* b2  = (const float*)d_in[16];
    const float* mW1 = (const float*)d_in[17];
    const float* mb1 = (const float*)d_in[18];
    const float* mW2 = (const float*)d_in[19];
    const float* mb2 = (const float*)d_in[20];
    float* out = (float*)d_out;

    float lrshift = logf(expm1f(0.01f));   // LR_SHIFT

    k_proj<<<BB*LL, 256>>>(x, Wq, bq, Wk, bk, Wv, bv, Wlr, blr, Wm, bm, Wd, bd, lrshift);
    k_fwd <<<BB*LL, 256>>>(W1, b1, W2, b2);
    k_scan<<<BB, LL>>>();
    k_A   <<<dim3(LL, BB), LL>>>();
    k_zq1 <<<BB*LL, 256>>>(W1, b1, mW1, mb1);
    k_zq2 <<<BB*LL, 256>>>(W2, b2, mW2, mb2, out);
    k_w1out<<<dim3(HH, BB), DD>>>(W1, mW1, out);
    k_w2out<<<dim3(DD, BB), HH>>>(W2, mW2, out);
    k_bout <<<BB, 256>>>(b1, mb1, b2, mb2, out);
}

// round 2
// speedup vs baseline: 3.0615x; 3.0615x over previous
#include <cuda_runtime.h>
#include <math.h>

#define BB 2
#define LL 128
#define DD 256
#define HH 256

// Output offsets (floats) in the packed d_out, reference tuple order.
#define OFF_ZQ2   0
#define OFF_W1P   65536
#define OFF_B1P   196608
#define OFF_W2P   197120
#define OFF_B2P   328192
#define OFF_MGW1  328704
#define OFF_MGB1  459776
#define OFF_MGW2  460288
#define OFF_MGB2  591360

// Scratch (device globals: allocation-free)
__device__ float g_q[BB*LL*DD];
__device__ float g_k[BB*LL*DD];
__device__ float g_v[BB*LL*DD];
__device__ float g_lr[BB*LL];
__device__ float g_logmom[BB*LL];
__device__ float g_logwd[BB*LL];
__device__ float g_cm[BB*LL];
__device__ float g_cd[BB*LL];
__device__ float g_momcum[BB*LL];
__device__ float g_wdcum[BB*LL];
__device__ float g_c[BB*LL];
__device__ float g_A[BB*LL*LL];
__device__ float g_X2[BB*LL*HH];
__device__ float g_gz1[BB*LL*HH];
__device__ float g_gz2[BB*LL*DD];
__device__ float g_sq[BB*LL*HH];
// Transposed fast weights (for coalesced row-dot loops)
__device__ float g_W1T[BB*DD*HH];   // [b][d][h]  (W1 is [b][h][d])
__device__ float g_mW1T[BB*DD*HH];
__device__ float g_W2T[BB*HH*DD];   // [b][h][d]  (W2 is [b][d][h])
__device__ float g_mW2T[BB*HH*DD];

__device__ __forceinline__ float softplusf(float x){
    return fmaxf(x, 0.f) + log1pf(expf(-fabsf(x)));
}

// Tiled 256x256 transpose, per batch (blockIdx.z). in: [b][R][C] -> out: [b][C][R]
__global__ void k_transpose(const float* __restrict__ in, float* __restrict__ outp)
{
    __shared__ float tile[32][33];
    int b = blockIdx.z;
    int x = blockIdx.x*32 + threadIdx.x;
    int y = blockIdx.y*32 + threadIdx.y;
    tile[threadIdx.y][threadIdx.x] = in[b*65536 + y*256 + x];
    __syncthreads();
    int tx = blockIdx.y*32 + threadIdx.x;
    int ty = blockIdx.x*32 + threadIdx.y;
    outp[b*65536 + ty*256 + tx] = tile[threadIdx.x][threadIdx.y];
}

// K1: q,k,v projections + scalar gates. One block per (b,l). Coalesced (col access).
__global__ void k_proj(const float* __restrict__ x,
    const float* __restrict__ Wq, const float* __restrict__ bq,
    const float* __restrict__ Wk, const float* __restrict__ bk,
    const float* __restrict__ Wv, const float* __restrict__ bv,
    const float* __restrict__ Wlr, const float* __restrict__ blr,
    const float* __restrict__ Wm, const float* __restrict__ bm,
    const float* __restrict__ Wd, const float* __restrict__ bd,
    float lrshift)
{
    int bl = blockIdx.x;
    int t = threadIdx.x;
    __shared__ float xs[DD];
    __shared__ float r0[256], r1[256], r2[256];
    xs[t] = x[bl*DD + t];
    __syncthreads();
    float aq = 0.f, ak = 0.f, av = 0.f;
    #pragma unroll 4
    for (int i = 0; i < DD; i++){
        float xv = xs[i];
        aq = fmaf(xv, Wq[i*DD + t], aq);
        ak = fmaf(xv, Wk[i*DD + t], ak);
        av = fmaf(xv, Wv[i*DD + t], av);
    }
    g_q[bl*DD + t] = aq + bq[t];
    g_k[bl*DD + t] = ak + bk[t];
    g_v[bl*DD + t] = av + bv[t];
    r0[t] = xs[t] * Wlr[t];
    r1[t] = xs[t] * Wm[t];
    r2[t] = xs[t] * Wd[t];
    __syncthreads();
    for (int s = 128; s > 0; s >>= 1){
        if (t < s){ r0[t] += r0[t+s]; r1[t] += r1[t+s]; r2[t] += r2[t+s]; }
        __syncthreads();
    }
    if (t == 0){
        g_lr[bl]     = softplusf(r0[0] + blr[0] + lrshift);
        g_logmom[bl] = -softplusf(-(r1[0] + bm[0]));
        g_logwd[bl]  = -softplusf(r2[0] + bd[0]);
    }
}

// K2: fast-weight forward + per-token gradients. One block per (b,l). All coalesced.
__global__ void k_fwd(const float* __restrict__ W2,
                      const float* __restrict__ b1, const float* __restrict__ b2)
{
    int bl = blockIdx.x;
    int b = bl / LL;
    int t = threadIdx.x;
    __shared__ float krow[DD];
    __shared__ float x2s[HH];
    __shared__ float gz2s[DD];
    krow[t] = g_k[bl*DD + t];
    __syncthreads();
    // Z1[h=t] = sum_i W1T[b,i,t]*krow[i] + b1   (coalesced over t)
    const float* w1t = g_W1T + b*DD*HH + t;
    float z1 = b1[b*HH + t];
    #pragma unroll 4
    for (int i = 0; i < DD; i++) z1 = fmaf(w1t[i*HH], krow[i], z1);
    float sig = 1.f / (1.f + expf(-z1));
    float x2 = z1 * sig;
    x2s[t] = x2;
    __syncthreads();
    // Z2[d=t] = sum_h W2T[b,h,t]*x2s[h] + b2   (coalesced)
    const float* w2t = g_W2T + b*HH*DD + t;
    float z2 = b2[b*DD + t];
    #pragma unroll 4
    for (int h = 0; h < HH; h++) z2 = fmaf(w2t[h*DD], x2s[h], z2);
    float gz2 = z2 - g_v[bl*DD + t];
    gz2s[t] = gz2;
    g_gz2[bl*DD + t] = gz2;
    __syncthreads();
    // gx2[h=t] = sum_d gz2[d] * W2[b,d,t]  (coalesced over t in original layout)
    float gx2 = 0.f;
    const float* w2c = W2 + b*DD*HH + t;
    #pragma unroll 4
    for (int d = 0; d < DD; d++) gx2 = fmaf(gz2s[d], w2c[d*HH], gx2);
    float sb = x2 + sig * (1.f - x2);   // silu_backward with s=silu(z1)
    g_gz1[bl*HH + t] = gx2 * sb;
    g_X2[bl*HH + t] = x2;
}

// K3: inclusive cumsums of gates. One block per batch, L threads.
__global__ void k_scan()
{
    int b = blockIdx.x;
    int l = threadIdx.x;
    __shared__ float sm[LL], sd[LL];
    sm[l] = g_logmom[b*LL + l];
    sd[l] = g_logwd[b*LL + l];
    __syncthreads();
    float cm = 0.f, cd = 0.f;
    for (int i = 0; i <= l; i++){ cm += sm[i]; cd += sd[i]; }
    g_cm[b*LL + l] = cm;
    g_cd[b*LL + l] = cd;
    g_momcum[b*LL + l] = expf(cm);
    g_wdcum[b*LL + l]  = expf(cd);
}

// K4: A = Dm@M (lower-tri LxL), c = Dm@mom_cum. One block per (l,b), L threads.
__global__ void k_A()
{
    int l = blockIdx.x, b = blockIdx.y;
    int m = threadIdx.x;
    __shared__ float cm[LL], cd[LL], red[LL];
    cm[m] = g_cm[b*LL + m];
    cd[m] = g_cd[b*LL + m];
    __syncthreads();
    float a = 0.f;
    if (m <= l){
        float base = cd[l] - cm[m];
        float s = 0.f;
        for (int j = m; j <= l; j++) s += expf(base - cd[j] + cm[j]);
        a = s;
    }
    g_A[(b*LL + l)*LL + m] = a;
    red[m] = (m <= l) ? expf(cd[l] - cd[m] + cm[m]) : 0.f;
    __syncthreads();
    for (int s = 64; s > 0; s >>= 1){
        if (m < s) red[m] += red[m + s];
        __syncthreads();
    }
    if (m == 0) g_c[b*LL + l] = red[0];
}

// K5: Zq1 & sq. One block per (b,l). Warp-cooperative kq + transposed weight dots.
__global__ void k_zq1(const float* __restrict__ b1, const float* __restrict__ mb1)
{
    int bl = blockIdx.x;
    int b = bl / LL, l = bl % LL;
    int t = threadIdx.x;
    int w = t >> 5, lane = t & 31;
    __shared__ float qrow[DD];
    __shared__ float p1[LL];
    qrow[t] = g_q[bl*DD + t];
    __syncthreads();
    // Phase A: p1[m] = A[l,m]*lr[m]*(1 + k[m,:].q)  via warp-cooperative dots
    for (int m = w; m <= l; m += 8){
        const float* kr = g_k + (b*LL + m)*DD;
        float s = 0.f;
        #pragma unroll
        for (int i = lane; i < DD; i += 32) s = fmaf(kr[i], qrow[i], s);
        #pragma unroll
        for (int o = 16; o; o >>= 1) s += __shfl_xor_sync(0xffffffffu, s, o);
        if (lane == 0)
            p1[m] = g_A[(b*LL + l)*LL + m] * g_lr[b*LL + m] * (1.f + s);
    }
    __syncthreads();
    // Phase B
    float acc = 0.f;
    const float* gz = g_gz1 + b*LL*HH + t;
    for (int m = 0; m <= l; m++) acc = fmaf(p1[m], gz[m*HH], acc);
    const float* w1t  = g_W1T  + b*DD*HH + t;
    const float* mw1t = g_mW1T + b*DD*HH + t;
    float w1q = 0.f, mw1q = 0.f;
    #pragma unroll 4
    for (int i = 0; i < DD; i++){
        float qv = qrow[i];
        w1q  = fmaf(w1t[i*HH],  qv, w1q);
        mw1q = fmaf(mw1t[i*HH], qv, mw1q);
    }
    float cl = g_c[bl], wdl = g_wdcum[bl];
    float zq1 = acc - cl * (mw1q + mb1[b*HH + t]) + wdl * (w1q + b1[b*HH + t]);
    float sig = 1.f / (1.f + expf(-zq1));
    g_sq[bl*HH + t] = zq1 * sig;
}

// K6: Zq2 (first output block). One block per (b,l).
__global__ void k_zq2(const float* __restrict__ b2, const float* __restrict__ mb2,
                      float* __restrict__ out)
{
    int bl = blockIdx.x;
    int b = bl / LL, l = bl % LL;
    int t = threadIdx.x;
    int w = t >> 5, lane = t & 31;
    __shared__ float sqrow[HH];
    __shared__ float p2[LL];
    sqrow[t] = g_sq[bl*HH + t];
    __syncthreads();
    // Phase A: p2[m] = A[l,m]*lr[m]*(1 + X2[m,:].sq)
    for (int m = w; m <= l; m += 8){
        const float* xr = g_X2 + (b*LL + m)*HH;
        float s = 0.f;
        #pragma unroll
        for (int i = lane; i < HH; i += 32) s = fmaf(xr[i], sqrow[i], s);
        #pragma unroll
        for (int o = 16; o; o >>= 1) s += __shfl_xor_sync(0xffffffffu, s, o);
        if (lane == 0)
            p2[m] = g_A[(b*LL + l)*LL + m] * g_lr[b*LL + m] * (1.f + s);
    }
    __syncthreads();
    float acc = 0.f;
    const float* gz = g_gz2 + b*LL*DD + t;
    for (int m = 0; m <= l; m++) acc = fmaf(p2[m], gz[m*DD], acc);
    const float* w2t  = g_W2T  + b*HH*DD + t;
    const float* mw2t = g_mW2T + b*HH*DD + t;
    float w2s = 0.f, mw2s = 0.f;
    #pragma unroll 4
    for (int h = 0; h < HH; h++){
        float sv = sqrow[h];
        w2s  = fmaf(w2t[h*DD],  sv, w2s);
        mw2s = fmaf(mw2t[h*DD], sv, mw2s);
    }
    float cl = g_c[bl], wdl = g_wdcum[bl];
    out[OFF_ZQ2 + bl*DD + t] =
        acc - cl * (mw2s + mb2[b*DD + t]) + wdl * (w2s + b2[b*DD + t]);
}

// K7: last-token W1p / mgW1. One block per (b,h), D threads.
__global__ void k_w1out(const float* __restrict__ W1, const float* __restrict__ mW1,
                        float* __restrict__ out)
{
    int h = blockIdx.x, b = blockIdx.y;
    int t = threadIdx.x;
    __shared__ float ga[LL], gm[LL];
    const int rl = LL - 1;
    float cmL = g_cm[b*LL + rl];
    if (t < LL){
        float lr = g_lr[b*LL + t];
        float gz = g_gz1[(b*LL + t)*HH + h];
        ga[t] = g_A[(b*LL + rl)*LL + t] * lr * gz;
        gm[t] = expf(cmL - g_cm[b*LL + t]) * lr * gz;
    }
    __syncthreads();
    float s1 = 0.f, s2 = 0.f;
    const float* kp = g_k + b*LL*DD + t;
    #pragma unroll 4
    for (int m = 0; m < LL; m++){
        float kv = kp[m*DD];
        s1 = fmaf(ga[m], kv, s1);
        s2 = fmaf(gm[m], kv, s2);
    }
    float cL = g_c[b*LL + rl], wdL = g_wdcum[b*LL + rl], momL = g_momcum[b*LL + rl];
    float w1v  = W1[(b*HH + h)*DD + t];
    float mw1v = mW1[(b*HH + h)*DD + t];
    out[OFF_W1P  + (b*HH + h)*DD + t] = s1 - cL * mw1v + wdL * w1v;
    out[OFF_MGW1 + (b*HH + h)*DD + t] = s2 - momL * mw1v;
}

// K8: last-token W2p / mgW2. One block per (b,d), H threads.
__global__ void k_w2out(const float* __restrict__ W2, const float* __restrict__ mW2,
                        float* __restrict__ out)
{
    int d = blockIdx.x, b = blockIdx.y;
    int t = threadIdx.x;
    __shared__ float ga[LL], gm[LL];
    const int rl = LL - 1;
    float cmL = g_cm[b*LL + rl];
    if (t < LL){
        float lr = g_lr[b*LL + t];
        float gz = g_gz2[(b*LL + t)*DD + d];
        ga[t] = g_A[(b*LL + rl)*LL + t] * lr * gz;
        gm[t] = expf(cmL - g_cm[b*LL + t]) * lr * gz;
    }
    __syncthreads();
    float s1 = 0.f, s2 = 0.f;
    const float* xp = g_X2 + b*LL*HH + t;
    #pragma unroll 4
    for (int m = 0; m < LL; m++){
        float xv = xp[m*HH];
        s1 = fmaf(ga[m], xv, s1);
        s2 = fmaf(gm[m], xv, s2);
    }
    float cL = g_c[b*LL + rl], wdL = g_wdcum[b*LL + rl], momL = g_momcum[b*LL + rl];
    float w2v  = W2[(b*DD + d)*HH + t];
    float mw2v = mW2[(b*DD + d)*HH + t];
    out[OFF_W2P  + (b*DD + d)*HH + t] = s1 - cL * mw2v + wdL * w2v;
    out[OFF_MGW2 + (b*DD + d)*HH + t] = s2 - momL * mw2v;
}

// K9: last-token biases. One block per batch, 256 threads.
__global__ void k_bout(const float* __restrict__ b1, const float* __restrict__ mb1,
                       const float* __restrict__ b2, const float* __restrict__ mb2,
                       float* __restrict__ out)
{
    int b = blockIdx.x;
    int t = threadIdx.x;
    __shared__ float aw[LL], mw[LL];
    const int rl = LL - 1;
    if (t < LL){
        float lr = g_lr[b*LL + t];
        aw[t] = g_A[(b*LL + rl)*LL + t] * lr;
        mw[t] = expf(g_cm[b*LL + rl] - g_cm[b*LL + t]) * lr;
    }
    __syncthreads();
    float cL = g_c[b*LL + rl], wdL = g_wdcum[b*LL + rl], momL = g_momcum[b*LL + rl];
    float s1 = 0.f, s2 = 0.f;
    const float* gz1p = g_gz1 + b*LL*HH + t;
    #pragma unroll 4
    for (int m = 0; m < LL; m++){
        float g = gz1p[m*HH];
        s1 = fmaf(aw[m], g, s1);
        s2 = fmaf(mw[m], g, s2);
    }
    out[OFF_B1P  + b*HH + t] = s1 - cL * mb1[b*HH + t] + wdL * b1[b*HH + t];
    out[OFF_MGB1 + b*HH + t] = s2 - momL * mb1[b*HH + t];
    float s3 = 0.f, s4 = 0.f;
    const float* gz2p = g_gz2 + b*LL*DD + t;
    #pragma unroll 4
    for (int m = 0; m < LL; m++){
        float g = gz2p[m*DD];
        s3 = fmaf(aw[m], g, s3);
        s4 = fmaf(mw[m], g, s4);
    }
    out[OFF_B2P  + b*DD + t] = s3 - cL * mb2[b*DD + t] + wdL * b2[b*DD + t];
    out[OFF_MGB2 + b*DD + t] = s4 - momL * mb2[b*DD + t];
}

extern "C" void kernel_launch(void* const* d_in, const int* in_sizes, int n_in,
                              void* d_out, int out_size)
{
    const float* x   = (const float*)d_in[0];
    const float* Wq  = (const float*)d_in[1];
    const float* bq  = (const float*)d_in[2];
    const float* Wk  = (const float*)d_in[3];
    const float* bk  = (const float*)d_in[4];
    const float* Wv  = (const float*)d_in[5];
    const float* bv  = (const float*)d_in[6];
    const float* Wlr = (const float*)d_in[7];
    const float* blr = (const float*)d_in[8];
    const float* Wm  = (const float*)d_in[9];
    const float* bm  = (const float*)d_in[10];
    const float* Wd  = (const float*)d_in[11];
    const float* bd  = (const float*)d_in[12];
    const float* W1  = (const float*)d_in[13];
    const float* b1  = (const float*)d_in[14];
    const float* W2  = (const float*)d_in[15];
    const float* b2  = (const float*)d_in[16];
    const float* mW1 = (const float*)d_in[17];
    const float* mb1 = (const float*)d_in[18];
    const float* mW2 = (const float*)d_in[19];
    const float* mb2 = (const float*)d_in[20];
    float* out = (float*)d_out;

    float lrshift = logf(expm1f(0.01f));   // LR_SHIFT

    float* w1t; float* mw1t; float* w2t; float* mw2t;
    cudaGetSymbolAddress((void**)&w1t,  g_W1T);
    cudaGetSymbolAddress((void**)&mw1t, g_mW1T);
    cudaGetSymbolAddress((void**)&w2t,  g_W2T);
    cudaGetSymbolAddress((void**)&mw2t, g_mW2T);

    dim3 tgrid(8, 8, BB), tblk(32, 32);
    k_transpose<<<tgrid, tblk>>>(W1,  w1t);
    k_transpose<<<tgrid, tblk>>>(mW1, mw1t);
    k_transpose<<<tgrid, tblk>>>(W2,  w2t);
    k_transpose<<<tgrid, tblk>>>(mW2, mw2t);

    k_proj<<<BB*LL, 256>>>(x, Wq, bq, Wk, bk, Wv, bv, Wlr, blr, Wm, bm, Wd, bd, lrshift);
    k_fwd <<<BB*LL, 256>>>(W2, b1, b2);
    k_scan<<<BB, LL>>>();
    k_A   <<<dim3(LL, BB), LL>>>();
    k_zq1 <<<BB*LL, 256>>>(b1, mb1);
    k_zq2 <<<BB*LL, 256>>>(b2, mb2, out);
    k_w1out<<<dim3(HH, BB), DD>>>(W1, mW1, out);
    k_w2out<<<dim3(DD, BB), HH>>>(W2, mW2, out);
    k_bout <<<BB, 256>>>(b1, mb1, b2, mb2, out);
}

// round 3
// speedup vs baseline: 3.2627x; 1.0657x over previous
#include <cuda_runtime.h>
#include <math.h>

#define BB 2
#define LL 128
#define DD 256
#define HH 256

// Output offsets (floats) in the packed d_out, reference tuple order.
#define OFF_ZQ2   0
#define OFF_W1P   65536
#define OFF_B1P   196608
#define OFF_W2P   197120
#define OFF_B2P   328192
#define OFF_MGW1  328704
#define OFF_MGB1  459776
#define OFF_MGW2  460288
#define OFF_MGB2  591360

// Scratch (device globals: allocation-free)
__device__ float g_q[BB*LL*DD];
__device__ float g_k[BB*LL*DD];
__device__ float g_v[BB*LL*DD];
__device__ float g_lr[BB*LL];
__device__ float g_logmom[BB*LL];
__device__ float g_logwd[BB*LL];
__device__ float g_cm[BB*LL];
__device__ float g_cd[BB*LL];
__device__ float g_momcum[BB*LL];
__device__ float g_wdcum[BB*LL];
__device__ float g_c[BB*LL];
__device__ float g_A[BB*LL*LL];
__device__ float g_X2[BB*LL*HH];
__device__ float g_gz1[BB*LL*HH];
__device__ float g_gz2[BB*LL*DD];
__device__ float g_sq[BB*LL*HH];
// Transposed fast weights
__device__ float g_W1T[BB*DD*HH];   // [b][d][h]  (W1 is [b][h][d])
__device__ float g_mW1T[BB*DD*HH];
__device__ float g_W2T[BB*HH*DD];   // [b][h][d]  (W2 is [b][d][h])
__device__ float g_mW2T[BB*HH*DD];

__device__ __forceinline__ float softplusf(float x){
    return fmaxf(x, 0.f) + log1pf(__expf(-fabsf(x)));
}

// ============================================================================
// KA: 4 weight transposes (blocks 0..511) + q/k/v proj + gates (blocks 512..703)
// 256 threads.
// ============================================================================
__global__ void KA(const float* __restrict__ x,
    const float* __restrict__ Wq, const float* __restrict__ bq,
    const float* __restrict__ Wk, const float* __restrict__ bk,
    const float* __restrict__ Wv, const float* __restrict__ bv,
    const float* __restrict__ Wlr, const float* __restrict__ blr,
    const float* __restrict__ Wm, const float* __restrict__ bm,
    const float* __restrict__ Wd, const float* __restrict__ bd,
    const float* __restrict__ W1, const float* __restrict__ mW1,
    const float* __restrict__ W2, const float* __restrict__ mW2,
    float lrshift)
{
    __shared__ float sbuf[1056];
    int idx = blockIdx.x, t = threadIdx.x;
    if (idx < 512){
        // ---- transpose: mat in {W1,mW1,W2,mW2}, per batch, 32x32 tiles ----
        float (*tile)[33] = (float(*)[33])sbuf;
        int mat = idx >> 7, rem = idx & 127;
        int b = rem >> 6, tl = rem & 63;
        int by = tl >> 3, bx = tl & 7;
        const float* src = (mat==0)?W1:(mat==1)?mW1:(mat==2)?W2:mW2;
        float* dstp = ((mat==0)?g_W1T:(mat==1)?g_mW1T:(mat==2)?g_W2T:g_mW2T);
        src  += b*65536;
        dstp += b*65536;
        int tx = t & 31, ty = t >> 5;        // ty: 0..7
        #pragma unroll
        for (int i = 0; i < 4; i++)
            tile[ty+8*i][tx] = src[(by*32+ty+8*i)*256 + bx*32+tx];
        __syncthreads();
        #pragma unroll
        for (int i = 0; i < 4; i++)
            dstp[(bx*32+ty+8*i)*256 + by*32+tx] = tile[tx][ty+8*i];
    } else {
        // ---- proj: mat3 in {q,k,v}; 4 rows per block ----
        float (*xs)[256] = (float(*)[256])sbuf;
        int j = idx - 512;
        int mat3 = j >> 6, g = j & 63;
        int bl0 = 4*g;
        #pragma unroll
        for (int r = 0; r < 4; r++) xs[r][t] = x[(bl0+r)*DD + t];
        __syncthreads();
        // gates (first 4 warps of mat3==0 blocks), overlaps with main loop
        if (mat3 == 0){
            int w = t >> 5, lane = t & 31;
            if (w < 4){
                float s0=0.f, s1=0.f, s2=0.f;
                for (int i = lane; i < DD; i += 32){
                    float xv = xs[w][i];
                    s0 = fmaf(xv, Wlr[i], s0);
                    s1 = fmaf(xv, Wm[i],  s1);
                    s2 = fmaf(xv, Wd[i],  s2);
                }
                #pragma unroll
                for (int o = 16; o; o >>= 1){
                    s0 += __shfl_xor_sync(0xffffffffu, s0, o);
                    s1 += __shfl_xor_sync(0xffffffffu, s1, o);
                    s2 += __shfl_xor_sync(0xffffffffu, s2, o);
                }
                if (lane == 0){
                    int bl = bl0 + w;
                    g_lr[bl]     = softplusf(s0 + blr[0] + lrshift);
                    g_logmom[bl] = -softplusf(-(s1 + bm[0]));
                    g_logwd[bl]  = -softplusf(s2 + bd[0]);
                }
            }
        }
        const float* W    = (mat3==0)?Wq:(mat3==1)?Wk:Wv;
        const float* bias = (mat3==0)?bq:(mat3==1)?bk:bv;
        float* dst        = (mat3==0)?g_q:(mat3==1)?g_k:g_v;
        float a0=0.f, a1=0.f, a2=0.f, a3=0.f;
        #pragma unroll 4
        for (int i = 0; i < DD; i++){
            float w = W[i*DD + t];
            a0 = fmaf(xs[0][i], w, a0);
            a1 = fmaf(xs[1][i], w, a1);
            a2 = fmaf(xs[2][i], w, a2);
            a3 = fmaf(xs[3][i], w, a3);
        }
        float bb = bias[t];
        dst[(bl0+0)*DD + t] = a0 + bb;
        dst[(bl0+1)*DD + t] = a1 + bb;
        dst[(bl0+2)*DD + t] = a2 + bb;
        dst[(bl0+3)*DD + t] = a3 + bb;
    }
}

// ============================================================================
// KB: fast-weight fwd+grad (blocks 0..63, 4 rows each) + gate cumsums (64,65)
// 256 threads.
// ============================================================================
__global__ void KB(const float* __restrict__ W2,
                   const float* __restrict__ b1, const float* __restrict__ b2)
{
    __shared__ float sbuf[3*1024];
    int idx = blockIdx.x, t = threadIdx.x;
    if (idx < 64){
        float (*krow)[256] = (float(*)[256])(sbuf);
        float (*x2s)[256]  = (float(*)[256])(sbuf + 1024);
        float (*gz2s)[256] = (float(*)[256])(sbuf + 2048);
        int bl0 = 4*idx, b = bl0 >> 7;
        #pragma unroll
        for (int r = 0; r < 4; r++) krow[r][t] = g_k[(bl0+r)*DD + t];
        __syncthreads();
        // Z1 (coalesced over t via W1T)
        const float* w1t = g_W1T + b*65536 + t;
        float bv1 = b1[b*HH + t];
        float z0=bv1, z1=bv1, z2=bv1, z3=bv1;
        #pragma unroll 4
        for (int i = 0; i < DD; i++){
            float w = w1t[i*HH];
            z0 = fmaf(krow[0][i], w, z0);
            z1 = fmaf(krow[1][i], w, z1);
            z2 = fmaf(krow[2][i], w, z2);
            z3 = fmaf(krow[3][i], w, z3);
        }
        float sg0 = __fdividef(1.f, 1.f + __expf(-z0));
        float sg1 = __fdividef(1.f, 1.f + __expf(-z1));
        float sg2 = __fdividef(1.f, 1.f + __expf(-z2));
        float sg3 = __fdividef(1.f, 1.f + __expf(-z3));
        float x20 = z0*sg0, x21 = z1*sg1, x22 = z2*sg2, x23 = z3*sg3;
        x2s[0][t]=x20; x2s[1][t]=x21; x2s[2][t]=x22; x2s[3][t]=x23;
        __syncthreads();
        // Z2
        const float* w2t = g_W2T + b*65536 + t;
        float bv2 = b2[b*DD + t];
        float y0=bv2, y1=bv2, y2=bv2, y3=bv2;
        #pragma unroll 4
        for (int h = 0; h < HH; h++){
            float w = w2t[h*DD];
            y0 = fmaf(x2s[0][h], w, y0);
            y1 = fmaf(x2s[1][h], w, y1);
            y2 = fmaf(x2s[2][h], w, y2);
            y3 = fmaf(x2s[3][h], w, y3);
        }
        float gA = y0 - g_v[(bl0+0)*DD + t];
        float gB = y1 - g_v[(bl0+1)*DD + t];
        float gC = y2 - g_v[(bl0+2)*DD + t];
        float gD = y3 - g_v[(bl0+3)*DD + t];
        gz2s[0][t]=gA; gz2s[1][t]=gB; gz2s[2][t]=gC; gz2s[3][t]=gD;
        g_gz2[(bl0+0)*DD+t]=gA; g_gz2[(bl0+1)*DD+t]=gB;
        g_gz2[(bl0+2)*DD+t]=gC; g_gz2[(bl0+3)*DD+t]=gD;
        __syncthreads();
        // gx2 (coalesced via original W2 layout)
        const float* w2c = W2 + b*65536 + t;
        float q0=0.f, q1=0.f, q2=0.f, q3=0.f;
        #pragma unroll 4
        for (int d = 0; d < DD; d++){
            float w = w2c[d*HH];
            q0 = fmaf(gz2s[0][d], w, q0);
            q1 = fmaf(gz2s[1][d], w, q1);
            q2 = fmaf(gz2s[2][d], w, q2);
            q3 = fmaf(gz2s[3][d], w, q3);
        }
        float sb0 = x20 + sg0*(1.f-x20);
        float sb1 = x21 + sg1*(1.f-x21);
        float sb2 = x22 + sg2*(1.f-x22);
        float sb3 = x23 + sg3*(1.f-x23);
        g_gz1[(bl0+0)*HH+t] = q0*sb0;  g_X2[(bl0+0)*HH+t] = x20;
        g_gz1[(bl0+1)*HH+t] = q1*sb1;  g_X2[(bl0+1)*HH+t] = x21;
        g_gz1[(bl0+2)*HH+t] = q2*sb2;  g_X2[(bl0+2)*HH+t] = x22;
        g_gz1[(bl0+3)*HH+t] = q3*sb3;  g_X2[(bl0+3)*HH+t] = x23;
    } else {
        // gate cumsums, one block per batch
        int b = idx - 64;
        float* sm = sbuf; float* sd = sbuf + 128;
        if (t < LL){ sm[t] = g_logmom[b*LL + t]; sd[t] = g_logwd[b*LL + t]; }
        __syncthreads();
        if (t < LL){
            float cm = 0.f, cd = 0.f;
            for (int i = 0; i <= t; i++){ cm += sm[i]; cd += sd[i]; }
            g_cm[b*LL + t] = cm;
            g_cd[b*LL + t] = cd;
            g_momcum[b*LL + t] = __expf(cm);
            g_wdcum[b*LL + t]  = __expf(cd);
        }
    }
}

// ============================================================================
// KC: A = Dm@M (lower-tri LxL), c = Dm@mom_cum. grid (LL,BB), 128 threads.
// ============================================================================
__global__ void KC()
{
    int l = blockIdx.x, b = blockIdx.y;
    int m = threadIdx.x;
    __shared__ float cm[LL], cd[LL], red[LL];
    cm[m] = g_cm[b*LL + m];
    cd[m] = g_cd[b*LL + m];
    __syncthreads();
    float a = 0.f;
    if (m <= l){
        float base = cd[l] - cm[m];
        float s = 0.f;
        for (int j = m; j <= l; j++) s += __expf(base - cd[j] + cm[j]);
        a = s;
    }
    g_A[(b*LL + l)*LL + m] = a;
    red[m] = (m <= l) ? __expf(cd[l] - cd[m] + cm[m]) : 0.f;
    __syncthreads();
    for (int s = 64; s > 0; s >>= 1){
        if (m < s) red[m] += red[m + s];
        __syncthreads();
    }
    if (m == 0) g_c[b*LL + l] = red[0];
}

// ============================================================================
// KD: zq1 (blocks 0..63) + w1out (64..191) + w2out (192..319) + bout (320,321)
// 256 threads.
// ============================================================================
__global__ void KD(const float* __restrict__ b1, const float* __restrict__ mb1,
                   const float* __restrict__ b2, const float* __restrict__ mb2,
                   const float* __restrict__ W1, const float* __restrict__ mW1,
                   const float* __restrict__ W2, const float* __restrict__ mW2,
                   float* __restrict__ out)
{
    __shared__ float sbuf[1536];
    int idx = blockIdx.x, t = threadIdx.x;
    const int rl = LL - 1;
    if (idx < 64){
        // ---- zq1, 4 rows per block ----
        float (*qrow)[256] = (float(*)[256])sbuf;
        float (*p1)[128]   = (float(*)[128])(sbuf + 1024);
        int bl0 = 4*idx, b = bl0 >> 7, l0 = bl0 & 127;
        int lmax = l0 + 3;
        #pragma unroll
        for (int r = 0; r < 4; r++) qrow[r][t] = g_q[(bl0+r)*DD + t];
        if (t < 128){ p1[0][t]=0.f; p1[1][t]=0.f; p1[2][t]=0.f; p1[3][t]=0.f; }
        __syncthreads();
        int w = t >> 5, lane = t & 31;
        for (int m = w; m <= lmax; m += 8){
            const float* kr = g_k + (b*LL + m)*DD;
            float s0=0.f, s1=0.f, s2=0.f, s3=0.f;
            for (int i = lane; i < DD; i += 32){
                float kv = kr[i];
                s0 = fmaf(kv, qrow[0][i], s0);
                s1 = fmaf(kv, qrow[1][i], s1);
                s2 = fmaf(kv, qrow[2][i], s2);
                s3 = fmaf(kv, qrow[3][i], s3);
            }
            #pragma unroll
            for (int o = 16; o; o >>= 1){
                s0 += __shfl_xor_sync(0xffffffffu, s0, o);
                s1 += __shfl_xor_sync(0xffffffffu, s1, o);
                s2 += __shfl_xor_sync(0xffffffffu, s2, o);
                s3 += __shfl_xor_sync(0xffffffffu, s3, o);
            }
            if (lane == 0){
                float lrm = g_lr[b*LL + m];
                const float* Ab = g_A + (b*LL + l0)*LL + m;
                if (m <= l0  ) p1[0][m] = Ab[0]      * lrm * (1.f + s0);
                if (m <= l0+1) p1[1][m] = Ab[LL]     * lrm * (1.f + s1);
                if (m <= l0+2) p1[2][m] = Ab[2*LL]   * lrm * (1.f + s2);
                               p1[3][m] = Ab[3*LL]   * lrm * (1.f + s3);
            }
        }
        __syncthreads();
        float a0=0.f, a1=0.f, a2=0.f, a3=0.f;
        const float* gz = g_gz1 + b*LL*HH + t;
        for (int m = 0; m <= lmax; m++){
            float gv = gz[m*HH];
            a0 = fmaf(p1[0][m], gv, a0);
            a1 = fmaf(p1[1][m], gv, a1);
            a2 = fmaf(p1[2][m], gv, a2);
            a3 = fmaf(p1[3][m], gv, a3);
        }
        const float* w1t  = g_W1T  + b*65536 + t;
        const float* mw1t = g_mW1T + b*65536 + t;
        float u0=0.f,u1=0.f,u2=0.f,u3=0.f, v0=0.f,v1=0.f,v2=0.f,v3=0.f;
        #pragma unroll 2
        for (int i = 0; i < DD; i++){
            float wv = w1t[i*HH], mv = mw1t[i*HH];
            float q0 = qrow[0][i], q1 = qrow[1][i], q2 = qrow[2][i], q3 = qrow[3][i];
            u0 = fmaf(q0, wv, u0); v0 = fmaf(q0, mv, v0);
            u1 = fmaf(q1, wv, u1); v1 = fmaf(q1, mv, v1);
            u2 = fmaf(q2, wv, u2); v2 = fmaf(q2, mv, v2);
            u3 = fmaf(q3, wv, u3); v3 = fmaf(q3, mv, v3);
        }
        float mb = mb1[b*HH + t], bbv = b1[b*HH + t];
        #pragma unroll
        for (int r = 0; r < 4; r++){
            int bl = bl0 + r;
            float accv = (r==0)?a0:(r==1)?a1:(r==2)?a2:a3;
            float wqv  = (r==0)?u0:(r==1)?u1:(r==2)?u2:u3;
            float mqv  = (r==0)?v0:(r==1)?v1:(r==2)?v2:v3;
            float z = accv - g_c[bl]*(mqv + mb) + g_wdcum[bl]*(wqv + bbv);
            float sg = __fdividef(1.f, 1.f + __expf(-z));
            g_sq[bl*HH + t] = z*sg;
        }
    } else if (idx < 192){
        // ---- w1out: 4 h per block ----
        int jj = idx - 64;
        int b = jj >> 6, h0 = 4*(jj & 63);
        float (*ga)[128] = (float(*)[128])sbuf;
        float (*gm)[128] = (float(*)[128])(sbuf + 512);
        float cmL = g_cm[b*LL + rl];
        if (t < 128){
            int m = t;
            float lrm = g_lr[b*LL + m];
            float Av = g_A[(b*LL + rl)*LL + m]*lrm;
            float Mv = __expf(cmL - g_cm[b*LL + m])*lrm;
            float4 g4 = *(const float4*)(g_gz1 + (b*LL + m)*HH + h0);
            ga[0][m]=Av*g4.x; ga[1][m]=Av*g4.y; ga[2][m]=Av*g4.z; ga[3][m]=Av*g4.w;
            gm[0][m]=Mv*g4.x; gm[1][m]=Mv*g4.y; gm[2][m]=Mv*g4.z; gm[3][m]=Mv*g4.w;
        }
        __syncthreads();
        float s10=0.f,s11=0.f,s12=0.f,s13=0.f, s20=0.f,s21=0.f,s22=0.f,s23=0.f;
        const float* kp = g_k + b*LL*DD + t;
        #pragma unroll 2
        for (int m = 0; m < LL; m++){
            float kv = kp[m*DD];
            s10 = fmaf(ga[0][m], kv, s10); s20 = fmaf(gm[0][m], kv, s20);
            s11 = fmaf(ga[1][m], kv, s11); s21 = fmaf(gm[1][m], kv, s21);
            s12 = fmaf(ga[2][m], kv, s12); s22 = fmaf(gm[2][m], kv, s22);
            s13 = fmaf(ga[3][m], kv, s13); s23 = fmaf(gm[3][m], kv, s23);
        }
        float cL = g_c[b*LL+rl], wdL = g_wdcum[b*LL+rl], momL = g_momcum[b*LL+rl];
        #pragma unroll
        for (int r = 0; r < 4; r++){
            int h = h0 + r;
            float s1v = (r==0)?s10:(r==1)?s11:(r==2)?s12:s13;
            float s2v = (r==0)?s20:(r==1)?s21:(r==2)?s22:s23;
            float w1v  = W1[(b*HH + h)*DD + t];
            float mw1v = mW1[(b*HH + h)*DD + t];
            out[OFF_W1P  + (b*HH + h)*DD + t] = s1v - cL*mw1v + wdL*w1v;
            out[OFF_MGW1 + (b*HH + h)*DD + t] = s2v - momL*mw1v;
        }
    } else if (idx < 320){
        // ---- w2out: 4 d per block ----
        int jj = idx - 192;
        int b = jj >> 6, d0 = 4*(jj & 63);
        float (*ga)[128] = (float(*)[128])sbuf;
        float (*gm)[128] = (float(*)[128])(sbuf + 512);
        float cmL = g_cm[b*LL + rl];
        if (t < 128){
            int m = t;
            float lrm = g_lr[b*LL + m];
            float Av = g_A[(b*LL + rl)*LL + m]*lrm;
            float Mv = __expf(cmL - g_cm[b*LL + m])*lrm;
            float4 g4 = *(const float4*)(g_gz2 + (b*LL + m)*DD + d0);
            ga[0][m]=Av*g4.x; ga[1][m]=Av*g4.y; ga[2][m]=Av*g4.z; ga[3][m]=Av*g4.w;
            gm[0][m]=Mv*g4.x; gm[1][m]=Mv*g4.y; gm[2][m]=Mv*g4.z; gm[3][m]=Mv*g4.w;
        }
        __syncthreads();
        float s10=0.f,s11=0.f,s12=0.f,s13=0.f, s20=0.f,s21=0.f,s22=0.f,s23=0.f;
        const float* xp = g_X2 + b*LL*HH + t;
        #pragma unroll 2
        for (int m = 0; m < LL; m++){
            float xv = xp[m*HH];
            s10 = fmaf(ga[0][m], xv, s10); s20 = fmaf(gm[0][m], xv, s20);
            s11 = fmaf(ga[1][m], xv, s11); s21 = fmaf(gm[1][m], xv, s21);
            s12 = fmaf(ga[2][m], xv, s12); s22 = fmaf(gm[2][m], xv, s22);
            s13 = fmaf(ga[3][m], xv, s13); s23 = fmaf(gm[3][m], xv, s23);
        }
        float cL = g_c[b*LL+rl], wdL = g_wdcum[b*LL+rl], momL = g_momcum[b*LL+rl];
        #pragma unroll
        for (int r = 0; r < 4; r++){
            int d = d0 + r;
            float s1v = (r==0)?s10:(r==1)?s11:(r==2)?s12:s13;
            float s2v = (r==0)?s20:(r==1)?s21:(r==2)?s22:s23;
            float w2v  = W2[(b*DD + d)*HH + t];
            float mw2v = mW2[(b*DD + d)*HH + t];
            out[OFF_W2P  + (b*DD + d)*HH + t] = s1v - cL*mw2v + wdL*w2v;
            out[OFF_MGW2 + (b*DD + d)*HH + t] = s2v - momL*mw2v;
        }
    } else {
        // ---- bout: one block per batch ----
        int b = idx - 320;
        float* aw = sbuf; float* mw = sbuf + 128;
        if (t < 128){
            float lrm = g_lr[b*LL + t];
            aw[t] = g_A[(b*LL + rl)*LL + t]*lrm;
            mw[t] = __expf(g_cm[b*LL + rl] - g_cm[b*LL + t])*lrm;
        }
        __syncthreads();
        float cL = g_c[b*LL+rl], wdL = g_wdcum[b*LL+rl], momL = g_momcum[b*LL+rl];
        float s1=0.f, s2=0.f;
        const float* gz1p = g_gz1 + b*LL*HH + t;
        #pragma unroll 4
        for (int m = 0; m < LL; m++){
            float g = gz1p[m*HH];
            s1 = fmaf(aw[m], g, s1);
            s2 = fmaf(mw[m], g, s2);
        }
        out[OFF_B1P  + b*HH + t] = s1 - cL*mb1[b*HH + t] + wdL*b1[b*HH + t];
        out[OFF_MGB1 + b*HH + t] = s2 - momL*mb1[b*HH + t];
        float s3=0.f, s4=0.f;
        const float* gz2p = g_gz2 + b*LL*DD + t;
        #pragma unroll 4
        for (int m = 0; m < LL; m++){
            float g = gz2p[m*DD];
            s3 = fmaf(aw[m], g, s3);
            s4 = fmaf(mw[m], g, s4);
        }
        out[OFF_B2P  + b*DD + t] = s3 - cL*mb2[b*DD + t] + wdL*b2[b*DD + t];
        out[OFF_MGB2 + b*DD + t] = s4 - momL*mb2[b*DD + t];
    }
}

// ============================================================================
// KE: zq2, 4 rows per block, 64 blocks, 256 threads.
// ============================================================================
__global__ void KE(const float* __restrict__ b2, const float* __restrict__ mb2,
                   float* __restrict__ out)
{
    __shared__ float sbuf[1536];
    float (*sqr)[256] = (float(*)[256])sbuf;
    float (*p2)[128]  = (float(*)[128])(sbuf + 1024);
    int idx = blockIdx.x, t = threadIdx.x;
    int bl0 = 4*idx, b = bl0 >> 7, l0 = bl0 & 127;
    int lmax = l0 + 3;
    #pragma unroll
    for (int r = 0; r < 4; r++) sqr[r][t] = g_sq[(bl0+r)*HH + t];
    if (t < 128){ p2[0][t]=0.f; p2[1][t]=0.f; p2[2][t]=0.f; p2[3][t]=0.f; }
    __syncthreads();
    int w = t >> 5, lane = t & 31;
    for (int m = w; m <= lmax; m += 8){
        const float* xr = g_X2 + (b*LL + m)*HH;
        float s0=0.f, s1=0.f, s2=0.f, s3=0.f;
        for (int i = lane; i < HH; i += 32){
            float xv = xr[i];
            s0 = fmaf(xv, sqr[0][i], s0);
            s1 = fmaf(xv, sqr[1][i], s1);
            s2 = fmaf(xv, sqr[2][i], s2);
            s3 = fmaf(xv, sqr[3][i], s3);
        }
        #pragma unroll
        for (int o = 16; o; o >>= 1){
            s0 += __shfl_xor_sync(0xffffffffu, s0, o);
            s1 += __shfl_xor_sync(0xffffffffu, s1, o);
            s2 += __shfl_xor_sync(0xffffffffu, s2, o);
            s3 += __shfl_xor_sync(0xffffffffu, s3, o);
        }
        if (lane == 0){
            float lrm = g_lr[b*LL + m];
            const float* Ab = g_A + (b*LL + l0)*LL + m;
            if (m <= l0  ) p2[0][m] = Ab[0]    * lrm * (1.f + s0);
            if (m <= l0+1) p2[1][m] = Ab[LL]   * lrm * (1.f + s1);
            if (m <= l0+2) p2[2][m] = Ab[2*LL] * lrm * (1.f + s2);
                           p2[3][m] = Ab[3*LL] * lrm * (1.f + s3);
        }
    }
    __syncthreads();
    float a0=0.f, a1=0.f, a2=0.f, a3=0.f;
    const float* gz = g_gz2 + b*LL*DD + t;
    for (int m = 0; m <= lmax; m++){
        float gv = gz[m*DD];
        a0 = fmaf(p2[0][m], gv, a0);
        a1 = fmaf(p2[1][m], gv, a1);
        a2 = fmaf(p2[2][m], gv, a2);
        a3 = fmaf(p2[3][m], gv, a3);
    }
    const float* w2t  = g_W2T  + b*65536 + t;
    const float* mw2t = g_mW2T + b*65536 + t;
    float u0=0.f,u1=0.f,u2=0.f,u3=0.f, v0=0.f,v1=0.f,v2=0.f,v3=0.f;
    #pragma unroll 2
    for (int h = 0; h < HH; h++){
        float wv = w2t[h*DD], mv = mw2t[h*DD];
        float q0 = sqr[0][h], q1 = sqr[1][h], q2 = sqr[2][h], q3 = sqr[3][h];
        u0 = fmaf(q0, wv, u0); v0 = fmaf(q0, mv, v0);
        u1 = fmaf(q1, wv, u1); v1 = fmaf(q1, mv, v1);
        u2 = fmaf(q2, wv, u2); v2 = fmaf(q2, mv, v2);
        u3 = fmaf(q3, wv, u3); v3 = fmaf(q3, mv, v3);
    }
    float mb = mb2[b*DD + t], bbv = b2[b*DD + t];
    #pragma unroll
    for (int r = 0; r < 4; r++){
        int bl = bl0 + r;
        float accv = (r==0)?a0:(r==1)?a1:(r==2)?a2:a3;
        float wsv  = (r==0)?u0:(r==1)?u1:(r==2)?u2:u3;
        float msv  = (r==0)?v0:(r==1)?v1:(r==2)?v2:v3;
        out[OFF_ZQ2 + bl*DD + t] =
            accv - g_c[bl]*(msv + mb) + g_wdcum[bl]*(wsv + bbv);
    }
}

extern "C" void kernel_launch(void* const* d_in, const int* in_sizes, int n_in,
                              void* d_out, int out_size)
{
    const float* x   = (const float*)d_in[0];
    const float* Wq  = (const float*)d_in[1];
    const float* bq  = (const float*)d_in[2];
    const float* Wk  = (const float*)d_in[3];
    const float* bk  = (const float*)d_in[4];
    const float* Wv  = (const float*)d_in[5];
    const float* bv  = (const float*)d_in[6];
    const float* Wlr = (const float*)d_in[7];
    const float* blr = (const float*)d_in[8];
    const float* Wm  = (const float*)d_in[9];
    const float* bm  = (const float*)d_in[10];
    const float* Wd  = (const float*)d_in[11];
    const float* bd  = (const float*)d_in[12];
    const float* W1  = (const float*)d_in[13];
    const float* b1  = (const float*)d_in[14];
    const float* W2  = (const float*)d_in[15];
    const float* b2  = (const float*)d_in[16];
    const float* mW1 = (const float*)d_in[17];
    const float* mb1 = (const float*)d_in[18];
    const float* mW2 = (const float*)d_in[19];
    const float* mb2 = (const float*)d_in[20];
    float* out = (float*)d_out;

    float lrshift = logf(expm1f(0.01f));   // LR_SHIFT

    KA<<<704, 256>>>(x, Wq, bq, Wk, bk, Wv, bv, Wlr, blr, Wm, bm, Wd, bd,
                     W1, mW1, W2, mW2, lrshift);
    KB<<<66, 256>>>(W2, b1, b2);
    KC<<<dim3(LL, BB), LL>>>();
    KD<<<322, 256>>>(b1, mb1, b2, mb2, W1, mW1, W2, mW2, out);
    KE<<<64, 256>>>(b2, mb2, out);
}